// round 10
// baseline (speedup 1.0000x reference)
#include <cuda_runtime.h>
#include <math.h>

#define QLEN  1024
#define BATCH 4
#define DMODEL 1024
#define NH    16
#define HD    64
#define MEMLEN 512
#define KLEN  1536
#define MLPD  4096
#define QKV3  3072
#define ATT_SCALE 0.125f
#define LNEPS 1e-5f

// ---------------- scratch (static device globals; no allocation) ----------------
__device__ unsigned g_cat_t [(size_t)KLEN * BATCH * DMODEL];
__device__ unsigned g_qkv_t [(size_t)KLEN * BATCH * QKV3];
__device__ unsigned g_rp_t  [(size_t)KLEN * DMODEL];
__device__ float    g_BD    [(size_t)BATCH * NH * QLEN * KLEN];
__device__ unsigned g_ctx_t [(size_t)QLEN * BATCH * DMODEL];
__device__ float    g_y     [(size_t)QLEN * BATCH * DMODEL];
__device__ float    g_x     [(size_t)QLEN * BATCH * DMODEL];
__device__ unsigned g_x_t   [(size_t)QLEN * BATCH * DMODEL];
__device__ unsigned g_h_t   [(size_t)QLEN * BATCH * MLPD];
__device__ float    g_y2    [(size_t)QLEN * BATCH * DMODEL];
__device__ unsigned g_wqkv_t[(size_t)DMODEL * QKV3];
__device__ unsigned g_wr_t  [(size_t)DMODEL * DMODEL];
__device__ unsigned g_wo_t  [(size_t)DMODEL * DMODEL];
__device__ unsigned g_w1_t  [(size_t)DMODEL * MLPD];
__device__ unsigned g_w2_t  [(size_t)MLPD * DMODEL];
__device__ unsigned g_r_t   [(size_t)KLEN * DMODEL];

// ---------------- helpers ----------------
__device__ __forceinline__ unsigned f2tf(float x) {
    unsigned r; asm("cvt.rna.tf32.f32 %0, %1;" : "=r"(r) : "f"(x)); return r;
}
__device__ __forceinline__ void mma8(float c[4],
    unsigned a0, unsigned a1, unsigned a2, unsigned a3, unsigned b0, unsigned b1) {
    asm volatile(
        "mma.sync.aligned.m16n8k8.row.col.f32.tf32.tf32.f32 "
        "{%0,%1,%2,%3},{%4,%5,%6,%7},{%8,%9},{%0,%1,%2,%3};"
        : "+f"(c[0]), "+f"(c[1]), "+f"(c[2]), "+f"(c[3])
        : "r"(a0), "r"(a1), "r"(a2), "r"(a3), "r"(b0), "r"(b1));
}
// tf32 fragment via ldmatrix: an 8x4-fp32 tile is an 8x8-b16 matrix whose
// post-load distribution (thread t -> row t/4, fp32-col t%4) IS the tf32 frag.
__device__ __forceinline__ void ldm4(unsigned &r0, unsigned &r1, unsigned &r2, unsigned &r3,
                                     unsigned addr) {
    asm volatile("ldmatrix.sync.aligned.m8n8.x4.shared.b16 {%0,%1,%2,%3}, [%4];"
        : "=r"(r0), "=r"(r1), "=r"(r2), "=r"(r3) : "r"(addr));
}
#define CPA(dst, src) asm volatile("cp.async.cg.shared.global [%0],[%1],16;\n" :: "r"(dst), "l"(src))
#define CPC()         asm volatile("cp.async.commit_group;\n")
#define CPW(n)        asm volatile("cp.async.wait_group %0;\n" :: "n"(n))

// ---------------- fused rounding: all weights + r + concat in ONE launch ------------
struct Seg { const float* s; unsigned* d; size_t n4; };
struct Segs8 { Seg v[8]; };
__global__ void round_all(Segs8 segs) {
    #pragma unroll 1
    for (int k = 0; k < 8; k++) {
        const float* s = segs.v[k].s;
        unsigned* d = segs.v[k].d;
        size_t n4 = segs.v[k].n4;
        for (size_t i = (size_t)blockIdx.x * blockDim.x + threadIdx.x; i < n4;
             i += (size_t)gridDim.x * blockDim.x) {
            float4 v = ((const float4*)s)[i];
            uint4 t = { f2tf(v.x), f2tf(v.y), f2tf(v.z), f2tf(v.w) };
            ((uint4*)d)[i] = t;
        }
    }
}

// ---------------- 3-stage cp.async tf32 GEMM, block 128x256, warp tile 64x64 --------
#define GAS 36
#define GBS 264
#define STG 3
__global__ __launch_bounds__(256, 1) void gemm_tf32(
    const unsigned* __restrict__ A, const unsigned* __restrict__ B,
    float* __restrict__ Cf, unsigned* __restrict__ Ct,
    const float* __restrict__ bias, int M, int N, int K, int relu, int qkvskip)
{
    extern __shared__ unsigned sm[];
    unsigned* As = sm;                       // [STG][128*GAS]
    unsigned* Bs = sm + STG * 128 * GAS;     // [STG][32*GBS]
    unsigned sA = (unsigned)__cvta_generic_to_shared(As);
    unsigned sB = (unsigned)__cvta_generic_to_shared(Bs);
    int tid = threadIdx.x, lane = tid & 31, warp = tid >> 5;
    int qid = lane >> 2, qt = lane & 3;
    int lrow = lane & 15, lcol = (lane & 16) >> 2;       // ldmatrix addr pattern
    int wm = (warp >> 2) * 64, wn = (warp & 3) * 64;
    int m0 = blockIdx.y * 128, n0 = blockIdx.x * 256;
    if (qkvskip && (m0 + 128 <= MEMLEN * BATCH) && (n0 < DMODEL)) return;

    float c[4][8][4];
    #pragma unroll
    for (int mi = 0; mi < 4; mi++)
        #pragma unroll
        for (int ni = 0; ni < 8; ni++)
            #pragma unroll
            for (int t = 0; t < 4; t++) c[mi][ni][t] = 0.0f;

    // per-stage tile load: A 128x32, B 32x256
    auto stage_load = [&](int kt, int s) {
        int kb = kt << 5;
        #pragma unroll
        for (int i = 0; i < 4; i++) {
            int id = tid + i * 256; int r = id >> 3, c4 = (id & 7) * 4;
            CPA(sA + (s * 128 * GAS + r * GAS + c4) * 4, A + (size_t)(m0 + r) * K + kb + c4);
        }
        #pragma unroll
        for (int i = 0; i < 8; i++) {
            int id = tid + i * 256; int r = id >> 6, c4 = (id & 63) * 4;
            CPA(sB + (s * 32 * GBS + r * GBS + c4) * 4, B + (size_t)(kb + r) * N + n0 + c4);
        }
    };

    int KT = K >> 5;
    stage_load(0, 0); CPC();
    if (KT > 1) stage_load(1, 1);
    CPC();

    for (int kt = 0; kt < KT; kt++) {
        CPW(1);
        __syncthreads();
        if (kt + 2 < KT) { stage_load(kt + 2, (kt + 2) % 3); CPC(); }
        int soff = (kt % 3) * 128 * GAS;
        const unsigned* Bsb = Bs + (kt % 3) * 32 * GBS;
        #pragma unroll
        for (int kk = 0; kk < 4; kk++) {
            unsigned a[4][4], bf[8][2];
            #pragma unroll
            for (int mi = 0; mi < 4; mi++)
                ldm4(a[mi][0], a[mi][1], a[mi][2], a[mi][3],
                     sA + (unsigned)((soff + (wm + mi * 16 + lrow) * GAS + kk * 8 + lcol) * 4));
            #pragma unroll
            for (int ni = 0; ni < 8; ni++) {
                int base = (kk * 8 + qt) * GBS + wn + ni * 8 + qid;
                bf[ni][0] = Bsb[base]; bf[ni][1] = Bsb[base + 4 * GBS];
            }
            #pragma unroll
            for (int mi = 0; mi < 4; mi++)
                #pragma unroll
                for (int ni = 0; ni < 8; ni++)
                    mma8(c[mi][ni], a[mi][0], a[mi][1], a[mi][2], a[mi][3],
                         bf[ni][0], bf[ni][1]);
        }
    }
    #pragma unroll
    for (int mi = 0; mi < 4; mi++) {
        int row = m0 + wm + mi * 16 + qid;
        #pragma unroll
        for (int ni = 0; ni < 8; ni++) {
            int col = n0 + wn + ni * 8 + qt * 2;
            float b0 = bias ? bias[col] : 0.0f;
            float b1 = bias ? bias[col + 1] : 0.0f;
            float v00 = c[mi][ni][0] + b0, v01 = c[mi][ni][1] + b1;
            float v10 = c[mi][ni][2] + b0, v11 = c[mi][ni][3] + b1;
            if (relu) { v00 = fmaxf(v00, 0.f); v01 = fmaxf(v01, 0.f);
                        v10 = fmaxf(v10, 0.f); v11 = fmaxf(v11, 0.f); }
            if (Ct) {
                Ct[(size_t)row * N + col]           = f2tf(v00);
                Ct[(size_t)row * N + col + 1]       = f2tf(v01);
                Ct[(size_t)(row + 8) * N + col]     = f2tf(v10);
                Ct[(size_t)(row + 8) * N + col + 1] = f2tf(v11);
            } else {
                Cf[(size_t)row * N + col]           = v00;
                Cf[(size_t)row * N + col + 1]       = v01;
                Cf[(size_t)(row + 8) * N + col]     = v10;
                Cf[(size_t)(row + 8) * N + col + 1] = v11;
            }
        }
    }
}

// ---------------- BD kernel: scatter-store pre-shifted scaled BD (v-add fused) ------
#define BDS 68
__global__ __launch_bounds__(256) void bd_tf32(
    const unsigned* __restrict__ qkv_t, const unsigned* __restrict__ rp,
    const float* __restrict__ vvec, float* __restrict__ BDs)
{
    int i0 = blockIdx.y * 128, j0 = blockIdx.x * 128;
    if (j0 + i0 <= QLEN - 256) return;   // all stored j < 0: tile dead
    extern __shared__ unsigned sm[];
    unsigned* Qs = sm;                 // [128][BDS]
    unsigned* Rs = sm + 128 * BDS;     // [128][BDS]
    unsigned sQ = (unsigned)__cvta_generic_to_shared(Qs);
    unsigned sR = (unsigned)__cvta_generic_to_shared(Rs);
    int tid = threadIdx.x, lane = tid & 31, warp = tid >> 5;
    int qid = lane >> 2, qt = lane & 3;
    int lrow = lane & 15, lcol = (lane & 16) >> 2;
    int wm = (warp >> 2) * 64, wn = (warp & 3) * 32;
    int bh = blockIdx.z, b = bh >> 4, h = bh & 15;

    #pragma unroll
    for (int i = 0; i < 8; i++) {
        int id = tid + i * 256; int r = id >> 4, c4 = (id & 15) * 4;
        uint4 q = *(const uint4*)(qkv_t + ((size_t)(MEMLEN + i0 + r) * BATCH + b) * QKV3 + h * 64 + c4);
        float4 vv = *(const float4*)(vvec + h * 64 + c4);
        uint4 t = { f2tf(__uint_as_float(q.x) + vv.x), f2tf(__uint_as_float(q.y) + vv.y),
                    f2tf(__uint_as_float(q.z) + vv.z), f2tf(__uint_as_float(q.w) + vv.w) };
        *(uint4*)&Qs[r * BDS + c4] = t;
        *(uint4*)&Rs[r * BDS + c4] =
            *(const uint4*)(rp + (size_t)(j0 + r) * DMODEL + h * 64 + c4);
    }
    __syncthreads();
    float c[4][4][4];
    #pragma unroll
    for (int mi = 0; mi < 4; mi++)
        #pragma unroll
        for (int ni = 0; ni < 4; ni++)
            #pragma unroll
            for (int t = 0; t < 4; t++) c[mi][ni][t] = 0.0f;
    #pragma unroll
    for (int kk = 0; kk < 8; kk++) {
        unsigned a[4][4], bf[4][2];
        #pragma unroll
        for (int mi = 0; mi < 4; mi++)
            ldm4(a[mi][0], a[mi][1], a[mi][2], a[mi][3],
                 sQ + (unsigned)(((wm + mi * 16 + lrow) * BDS + kk * 8 + lcol) * 4));
        #pragma unroll
        for (int ni2 = 0; ni2 < 2; ni2++)
            ldm4(bf[ni2 * 2][0], bf[ni2 * 2 + 1][0], bf[ni2 * 2][1], bf[ni2 * 2 + 1][1],
                 sR + (unsigned)(((wn + ni2 * 16 + lrow) * BDS + kk * 8 + lcol) * 4));
        #pragma unroll
        for (int mi = 0; mi < 4; mi++)
            #pragma unroll
            for (int ni = 0; ni < 4; ni++)
                mma8(c[mi][ni], a[mi][0], a[mi][1], a[mi][2], a[mi][3],
                     bf[ni][0], bf[ni][1]);
    }
    float* bdp = BDs + (size_t)bh * QLEN * KLEN;
    #pragma unroll
    for (int mi = 0; mi < 4; mi++) {
        #pragma unroll
        for (int half = 0; half < 2; half++) {
            int i = i0 + wm + mi * 16 + qid + half * 8;
            int jbase = j0 - (QLEN - 1) + i;
            #pragma unroll
            for (int ni = 0; ni < 4; ni++) {
                int j = jbase + wn + ni * 8 + qt * 2;
                float v0 = c[mi][ni][half * 2] * ATT_SCALE;
                float v1 = c[mi][ni][half * 2 + 1] * ATT_SCALE;
                if (j >= 0 && j < KLEN)         bdp[(size_t)i * KLEN + j]     = v0;
                if (j + 1 >= 0 && j + 1 < KLEN) bdp[(size_t)i * KLEN + j + 1] = v1;
            }
        }
    }
}

// ---------------- fused flash attention (row-per-warp, P in registers) ----------------
#define FQS 68
#define FKS 68
#define FVS 72
__global__ __launch_bounds__(256) void flash_attn(
    const unsigned* __restrict__ qkv_t, const float* __restrict__ uvec,
    const float* __restrict__ BDs, unsigned* __restrict__ ctx_t)
{
    extern __shared__ unsigned sm[];
    unsigned* Qs = sm;                       // [128][FQS]
    unsigned* Ks = Qs + 128 * FQS;           // [2][64][FKS]
    unsigned* Vs = Ks + 2 * 64 * FKS;        // [2][64][FVS]
    unsigned sQ = (unsigned)__cvta_generic_to_shared(Qs);
    unsigned sK = (unsigned)__cvta_generic_to_shared(Ks);
    unsigned sV = (unsigned)__cvta_generic_to_shared(Vs);

    int tid = threadIdx.x, lane = tid & 31, warp = tid >> 5;
    int qid = lane >> 2, qt = lane & 3;
    int lrow = lane & 15, lcol = (lane & 16) >> 2;
    int bh = blockIdx.y, b = bh >> 4, h = bh & 15;
    int i0 = blockIdx.x * 128;
    int r0 = warp * 16;

    #pragma unroll
    for (int i = 0; i < 8; i++) {
        int id = tid + i * 256; int r = id >> 4, c4 = (id & 15) * 4;
        uint4 q = *(const uint4*)(qkv_t + ((size_t)(MEMLEN + i0 + r) * BATCH + b) * QKV3 + h * 64 + c4);
        float4 uv = *(const float4*)(uvec + h * 64 + c4);
        uint4 t = { f2tf(__uint_as_float(q.x) + uv.x), f2tf(__uint_as_float(q.y) + uv.y),
                    f2tf(__uint_as_float(q.z) + uv.z), f2tf(__uint_as_float(q.w) + uv.w) };
        *(uint4*)&Qs[r * FQS + c4] = t;
    }

    int njt = i0 / 64 + 10;
    if (njt > KLEN / 64) njt = KLEN / 64;

    auto stage = [&](int jt, int bf) {
        int j0 = jt * 64;
        #pragma unroll
        for (int i = 0; i < 4; i++) {
            int id = tid + i * 256; int r = id >> 4, c4 = (id & 15) * 4;
            int w8 = r & 7;
            int keyp = j0 + (r & ~7) + (w8 >> 1) + (w8 & 1) * 4;   // kappa perm
            CPA(sK + ((bf * 64 + r) * FKS + c4) * 4,
                qkv_t + ((size_t)keyp * BATCH + b) * QKV3 + DMODEL + h * 64 + c4);
            CPA(sV + ((bf * 64 + r) * FVS + c4) * 4,
                qkv_t + ((size_t)(j0 + r) * BATCH + b) * QKV3 + 2 * DMODEL + h * 64 + c4);
        }
    };

    stage(0, 0); CPC();

    float m0 = -1e30f, m1 = -1e30f, l0 = 0.0f, l1 = 0.0f;
    float o[8][4];
    #pragma unroll
    for (int nt = 0; nt < 8; nt++)
        #pragma unroll
        for (int t = 0; t < 4; t++) o[nt][t] = 0.0f;

    const float* bdp = BDs + ((size_t)bh * QLEN + i0) * KLEN;
    int irow0 = i0 + r0 + qid, irow1 = irow0 + 8;

    for (int jt = 0; jt < njt; jt++) {
        int buf = jt & 1;
        int j0 = jt * 64;
        if (jt + 1 < njt) stage(jt + 1, buf ^ 1);
        CPC();
        CPW(1);
        __syncthreads();
        const unsigned* Vb = Vs + buf * 64 * FVS;
        unsigned sKb = sK + buf * 64 * FKS * 4;

        float s[8][4];
        #pragma unroll
        for (int nt = 0; nt < 8; nt++)
            #pragma unroll
            for (int t = 0; t < 4; t++) s[nt][t] = 0.0f;
        #pragma unroll
        for (int kk = 0; kk < 8; kk++) {
            unsigned a0, a1, a2, a3, bf[8][2];
            ldm4(a0, a1, a2, a3,
                 sQ + (unsigned)(((r0 + lrow) * FQS + kk * 8 + lcol) * 4));
            #pragma unroll
            for (int nt2 = 0; nt2 < 4; nt2++)
                ldm4(bf[nt2 * 2][0], bf[nt2 * 2 + 1][0], bf[nt2 * 2][1], bf[nt2 * 2 + 1][1],
                     sKb + (unsigned)(((nt2 * 16 + lrow) * FKS + kk * 8 + lcol) * 4));
            #pragma unroll
            for (int nt = 0; nt < 8; nt++)
                mma8(s[nt], a0, a1, a2, a3, bf[nt][0], bf[nt][1]);
        }

        int msk = (j0 + 63 > i0 + MEMLEN);
        float mx0 = -1e30f, mx1 = -1e30f;
        #pragma unroll
        for (int nt = 0; nt < 8; nt++) {
            int k0 = j0 + nt * 8 + qt, k1 = k0 + 4;
            float v0 = s[nt][0] * ATT_SCALE + bdp[(size_t)(r0 + qid) * KLEN + k0];
            float v1 = s[nt][1] * ATT_SCALE + bdp[(size_t)(r0 + qid) * KLEN + k1];
            float v2 = s[nt][2] * ATT_SCALE + bdp[(size_t)(r0 + qid + 8) * KLEN + k0];
            float v3 = s[nt][3] * ATT_SCALE + bdp[(size_t)(r0 + qid + 8) * KLEN + k1];
            if (msk) {
                if (k0 > irow0 + MEMLEN) v0 = -1e30f;
                if (k1 > irow0 + MEMLEN) v1 = -1e30f;
                if (k0 > irow1 + MEMLEN) v2 = -1e30f;
                if (k1 > irow1 + MEMLEN) v3 = -1e30f;
            }
            s[nt][0] = v0; s[nt][1] = v1; s[nt][2] = v2; s[nt][3] = v3;
            mx0 = fmaxf(mx0, fmaxf(v0, v1));
            mx1 = fmaxf(mx1, fmaxf(v2, v3));
        }
        mx0 = fmaxf(mx0, __shfl_xor_sync(0xffffffffu, mx0, 1));
        mx0 = fmaxf(mx0, __shfl_xor_sync(0xffffffffu, mx0, 2));
        mx1 = fmaxf(mx1, __shfl_xor_sync(0xffffffffu, mx1, 1));
        mx1 = fmaxf(mx1, __shfl_xor_sync(0xffffffffu, mx1, 2));
        float mn0 = fmaxf(m0, mx0), mn1 = fmaxf(m1, mx1);
        float al0 = __expf(m0 - mn0), al1 = __expf(m1 - mn1);
        m0 = mn0; m1 = mn1;
        #pragma unroll
        for (int nt = 0; nt < 8; nt++) {
            o[nt][0] *= al0; o[nt][1] *= al0;
            o[nt][2] *= al1; o[nt][3] *= al1;
        }
        float rs0 = 0.0f, rs1 = 0.0f;
        #pragma unroll
        for (int nt = 0; nt < 8; nt++) {
            float p0 = __expf(s[nt][0] - mn0);
            float p1 = __expf(s[nt][1] - mn0);
            float p2 = __expf(s[nt][2] - mn1);
            float p3 = __expf(s[nt][3] - mn1);
            rs0 += p0 + p1; rs1 += p2 + p3;
            s[nt][0] = __uint_as_float(f2tf(p0));
            s[nt][1] = __uint_as_float(f2tf(p1));
            s[nt][2] = __uint_as_float(f2tf(p2));
            s[nt][3] = __uint_as_float(f2tf(p3));
        }
        rs0 += __shfl_xor_sync(0xffffffffu, rs0, 1);
        rs0 += __shfl_xor_sync(0xffffffffu, rs0, 2);
        rs1 += __shfl_xor_sync(0xffffffffu, rs1, 1);
        rs1 += __shfl_xor_sync(0xffffffffu, rs1, 2);
        l0 = l0 * al0 + rs0;
        l1 = l1 * al1 + rs1;

        #pragma unroll
        for (int kc = 0; kc < 8; kc++) {
            unsigned a0 = __float_as_uint(s[kc][0]);
            unsigned a1 = __float_as_uint(s[kc][2]);
            unsigned a2 = __float_as_uint(s[kc][1]);
            unsigned a3 = __float_as_uint(s[kc][3]);
            #pragma unroll
            for (int nt = 0; nt < 8; nt++) {
                int bbase = (kc * 8 + qt) * FVS + nt * 8 + qid;
                mma8(o[nt], a0, a1, a2, a3, Vb[bbase], Vb[bbase + 4 * FVS]);
            }
        }
        __syncthreads();
    }

    float inv0 = 1.0f / l0, inv1 = 1.0f / l1;
    int row0 = i0 + r0 + qid;
    #pragma unroll
    for (int nt = 0; nt < 8; nt++) {
        int col = h * 64 + nt * 8 + qt * 2;
        unsigned* p0 = ctx_t + ((size_t)row0 * BATCH + b) * DMODEL + col;
        unsigned* p1 = ctx_t + ((size_t)(row0 + 8) * BATCH + b) * DMODEL + col;
        p0[0] = f2tf(o[nt][0] * inv0); p0[1] = f2tf(o[nt][1] * inv0);
        p1[0] = f2tf(o[nt][2] * inv1); p1[1] = f2tf(o[nt][3] * inv1);
    }
}

// ---------------- layernorm: out = LN(a + b) * g + beta (+ optional tf32 copy) ------
__global__ __launch_bounds__(256) void ln_kernel(
    const float* __restrict__ a, const float* __restrict__ bres,
    const float* __restrict__ g, const float* __restrict__ beta,
    float* __restrict__ out, unsigned* __restrict__ out_t)
{
    int row = blockIdx.x;
    int tid = threadIdx.x;
    const float* ap = a    + (size_t)row * DMODEL;
    const float* bp = bres + (size_t)row * DMODEL;
    float x[4];
    float sum = 0.0f;
    #pragma unroll
    for (int t = 0; t < 4; t++) {
        int c = tid + t * 256;
        x[t] = ap[c] + bp[c];
        sum += x[t];
    }
    __shared__ float red[256];
    red[tid] = sum; __syncthreads();
    for (int o = 128; o > 0; o >>= 1) {
        if (tid < o) red[tid] += red[tid + o];
        __syncthreads();
    }
    float mean = red[0] * (1.0f / DMODEL); __syncthreads();
    float vs = 0.0f;
    #pragma unroll
    for (int t = 0; t < 4; t++) { float d = x[t] - mean; vs += d * d; }
    red[tid] = vs; __syncthreads();
    for (int o = 128; o > 0; o >>= 1) {
        if (tid < o) red[tid] += red[tid + o];
        __syncthreads();
    }
    float inv = rsqrtf(red[0] * (1.0f / DMODEL) + LNEPS);
    #pragma unroll
    for (int t = 0; t < 4; t++) {
        int c = tid + t * 256;
        float v = (x[t] - mean) * inv * g[c] + beta[c];
        out[(size_t)row * DMODEL + c] = v;
        if (out_t) out_t[(size_t)row * DMODEL + c] = f2tf(v);
    }
}

// ---------------- launch ----------------
extern "C" void kernel_launch(void* const* d_in, const int* in_sizes, int n_in,
                              void* d_out, int out_size)
{
    const float* inputs = (const float*)d_in[0];
    const float* r      = (const float*)d_in[1];
    const float* u      = (const float*)d_in[2];
    const float* v      = (const float*)d_in[3];
    const float* mem    = (const float*)d_in[4];
    const float* W_qkv  = (const float*)d_in[6];
    const float* W_r    = (const float*)d_in[7];
    const float* W_o    = (const float*)d_in[8];
    const float* ln1_g  = (const float*)d_in[9];
    const float* ln1_b  = (const float*)d_in[10];
    const float* ln2_g  = (const float*)d_in[11];
    const float* ln2_b  = (const float*)d_in[12];
    const float* W1     = (const float*)d_in[13];
    const float* b1     = (const float*)d_in[14];
    const float* W2     = (const float*)d_in[15];
    const float* b2     = (const float*)d_in[16];
    float* out = (float*)d_out;

    unsigned *cat_t, *qkv_t, *rp_t, *ctx_t, *x_t, *h_t;
    unsigned *wqkv_t, *wr_t, *wo_t, *w1_t, *w2_t, *r_t;
    float *BDs, *y, *x, *y2;
    cudaGetSymbolAddress((void**)&cat_t,  g_cat_t);
    cudaGetSymbolAddress((void**)&qkv_t,  g_qkv_t);
    cudaGetSymbolAddress((void**)&rp_t,   g_rp_t);
    cudaGetSymbolAddress((void**)&BDs,    g_BD);
    cudaGetSymbolAddress((void**)&ctx_t,  g_ctx_t);
    cudaGetSymbolAddress((void**)&y,      g_y);
    cudaGetSymbolAddress((void**)&x,      g_x);
    cudaGetSymbolAddress((void**)&x_t,    g_x_t);
    cudaGetSymbolAddress((void**)&h_t,    g_h_t);
    cudaGetSymbolAddress((void**)&y2,     g_y2);
    cudaGetSymbolAddress((void**)&wqkv_t, g_wqkv_t);
    cudaGetSymbolAddress((void**)&wr_t,   g_wr_t);
    cudaGetSymbolAddress((void**)&wo_t,   g_wo_t);
    cudaGetSymbolAddress((void**)&w1_t,   g_w1_t);
    cudaGetSymbolAddress((void**)&w2_t,   g_w2_t);
    cudaGetSymbolAddress((void**)&r_t,    g_r_t);

    const int gemm_smem  = STG * (128 * GAS + 32 * GBS) * 4;
    const int bd_smem    = (2 * 128 * BDS) * 4;
    const int flash_smem = (128 * FQS + 2 * 64 * FKS + 2 * 64 * FVS) * 4;
    cudaFuncSetAttribute(gemm_tf32,  cudaFuncAttributeMaxDynamicSharedMemorySize, gemm_smem);
    cudaFuncSetAttribute(bd_tf32,    cudaFuncAttributeMaxDynamicSharedMemorySize, bd_smem);
    cudaFuncSetAttribute(flash_attn, cudaFuncAttributeMaxDynamicSharedMemorySize, flash_smem);

    // 0. one fused rounding launch: weights, r, and concat([mem; inputs])
    Segs8 segs;
    segs.v[0] = { W_qkv, wqkv_t, (size_t)DMODEL * QKV3 / 4 };
    segs.v[1] = { W1,    w1_t,   (size_t)DMODEL * MLPD / 4 };
    segs.v[2] = { W2,    w2_t,   (size_t)MLPD * DMODEL / 4 };
    segs.v[3] = { W_r,   wr_t,   (size_t)DMODEL * DMODEL / 4 };
    segs.v[4] = { W_o,   wo_t,   (size_t)DMODEL * DMODEL / 4 };
    segs.v[5] = { r,     r_t,    (size_t)KLEN * DMODEL / 4 };
    segs.v[6] = { mem,   cat_t,  (size_t)MEMLEN * BATCH * DMODEL / 4 };
    segs.v[7] = { inputs, cat_t + (size_t)MEMLEN * BATCH * DMODEL,
                  (size_t)QLEN * BATCH * DMODEL / 4 };
    round_all<<<2048, 256>>>(segs);

    // 1. qkv_t = cat_t @ W_qkv (tf32 out; Q-third skipped for mem rows)
    gemm_tf32<<<dim3(QKV3 / 256, (KLEN * BATCH) / 128), 256, gemm_smem>>>(
        cat_t, wqkv_t, nullptr, qkv_t, nullptr, KLEN * BATCH, QKV3, DMODEL, 0, 1);

    // 2. rp_t = r @ W_r (tf32 out)
    gemm_tf32<<<dim3(DMODEL / 256, KLEN / 128), 256, gemm_smem>>>(
        r_t, wr_t, nullptr, rp_t, nullptr, KLEN, DMODEL, DMODEL, 0, 0);

    // 3. BDs (pre-shifted, pre-scaled; v-add fused)
    bd_tf32<<<dim3(KLEN / 128, QLEN / 128, BATCH * NH), 256, bd_smem>>>(qkv_t, rp_t, v, BDs);

    // 4. fused flash attention -> ctx_t (u-add fused)
    flash_attn<<<dim3(QLEN / 128, BATCH * NH), 256, flash_smem>>>(qkv_t, u, BDs, ctx_t);

    // 5. y = ctx_t @ W_o (fp32 out)
    gemm_tf32<<<dim3(DMODEL / 256, (QLEN * BATCH) / 128), 256, gemm_smem>>>(
        ctx_t, wo_t, y, nullptr, nullptr, QLEN * BATCH, DMODEL, DMODEL, 0, 0);

    // 6. x = LN1(inputs + y)  (+ tf32 copy)
    ln_kernel<<<QLEN * BATCH, 256>>>(inputs, y, ln1_g, ln1_b, x, x_t);

    // 7. h_t = relu(x_t @ W1 + b1) (tf32 out)
    gemm_tf32<<<dim3(MLPD / 256, (QLEN * BATCH) / 128), 256, gemm_smem>>>(
        x_t, w1_t, nullptr, h_t, b1, QLEN * BATCH, MLPD, DMODEL, 1, 0);

    // 8. y2 = h_t @ W2 + b2 (fp32 out)
    gemm_tf32<<<dim3(DMODEL / 256, (QLEN * BATCH) / 128), 256, gemm_smem>>>(
        h_t, w2_t, y2, nullptr, b2, QLEN * BATCH, DMODEL, MLPD, 0, 0);

    // 9. out = LN2(x + y2)
    ln_kernel<<<QLEN * BATCH, 256>>>(x, y2, ln2_g, ln2_b, out, nullptr);
}